// round 14
// baseline (speedup 1.0000x reference)
#include <cuda_runtime.h>
#include <cuda_bf16.h>

// out shape: (B=8, C=256, H=128, W=128) fp32, row-major. Output is independent
// of the input tensor and identical across batches:
//   out[b,c,i,j] = c<128 ? trig_c(i) : trig_{c-128}(j)
//   trig_cc(p)   = (cc even ? sin : cos)(p * 10000^(-floor(cc/2)/128))
//
// FINAL — converged and fully bracketed. Reproduced seven times (e2e
// 23.008-23.296us; kernel 19.55-20.13us) at 6.7-6.9 TB/s write injection
// ≈ 99% of the HW-measured SM->LTS fabric write cap (~6300 B/cyc); model
// floor 19.4us. One block per (b,c) plane; 128 unique values computed once
// in smem (sincosf per thread); 16 float4 staged in registers, then burst
// as 16 back-to-back streaming STG.128 (.cs, evict-first).
//
// Complete design-space closure (all theory-predicted, all verified):
//   R2  TMA bulk stores:            -10% — LTS cap is path-independent
//   R4  8-deep bursts, occ 81%:     -19% — stores need burst depth, not
//                                   latency hiding; low occ is fine
//   R6  32-deep bursts, 1024 CTAs:  kernel-neutral, e2e -8% (wave tail)
//   R11 STG.256 (v8.f32):           neutral — issue% 12.4->10.6, BW flat;
//                                   proves the cap is fabric, not dispatch
//   R1->R3 .cs eviction hint:       +9% (kept)
//   R3/R5/R7/R8/R10/R13 (this):     at the fabric floor.
//   Rejected on model: st.global.wt (~2x worse, DRAM-bound), persistent
//   CTAs / 512-thread blocks (isomorphic stream structure, zero upside).

__global__ __launch_bounds__(256) void pe2d_kernel(float* __restrict__ out) {
    const int bc  = blockIdx.x;       // b*256 + c
    const int c   = bc & 255;
    const int tid = threadIdx.x;

    __shared__ float s[128];

    if (tid < 128) {
        const int cc    = c & 127;        // channel within half
        const int pairk = cc >> 1;        // floor(cc/2)
        const float LOG2_10000 = 13.28771237954945f;
        float inv_dim = exp2f(-(float)pairk * (LOG2_10000 / 128.0f));
        float arg = (float)tid * inv_dim; // tid = position (i or j)
        float sv, cv;
        sincosf(arg, &sv, &cv);
        s[tid] = (cc & 1) ? cv : sv;
    }
    __syncthreads();

    // Per-thread: 16 float4 stores, consecutive lanes -> consecutive float4
    // (512B per warp per store, fully coalesced). Stage all values in
    // registers FIRST, then burst the 16 streaming stores back-to-back so the
    // LSU/L2 write queue stays saturated with no interleaved LDS/index math.
    float4 v[16];
    if (c < 128) {
        // value constant along j: row index = idx4 >> 5
        #pragma unroll
        for (int t = 0; t < 16; t++) {
            const int row = (tid + t * 256) >> 5;   // warp-uniform
            const float x = s[row];                 // smem broadcast
            v[t] = make_float4(x, x, x, x);
        }
    } else {
        // value varies along j only: every row replicates s[0..127]
        const float4* s4 = reinterpret_cast<const float4*>(s);
        #pragma unroll
        for (int t = 0; t < 16; t++) {
            v[t] = s4[(tid + t * 256) & 31];        // conflict-free LDS.128
        }
    }

    float4* outp = reinterpret_cast<float4*>(out) + (size_t)bc * 4096 + tid;
    #pragma unroll
    for (int t = 0; t < 16; t++) {
        __stcs(outp + t * 256, v[t]);               // st.global.cs.v4 (evict-first)
    }
}

extern "C" void kernel_launch(void* const* d_in, const int* in_sizes, int n_in,
                              void* d_out, int out_size) {
    (void)d_in; (void)in_sizes; (void)n_in; (void)out_size;
    // 8 batches * 256 channels = 2048 planes
    pe2d_kernel<<<2048, 256>>>((float*)d_out);
}

// round 15
// speedup vs baseline: 1.0931x; 1.0931x over previous
#include <cuda_runtime.h>
#include <cuda_bf16.h>

// out shape: (B=8, C=256, H=128, W=128) fp32, row-major. Output is independent
// of the input tensor and identical across batches:
//   out[b,c,i,j] = c<128 ? trig_c(i) : trig_{c-128}(j)
//   trig_cc(p)   = (cc even ? sin : cos)(p * 10000^(-floor(cc/2)/128))
//
// FINAL — converged and fully bracketed. Eight holds: kernel 19.55-20.29us,
// e2e 23.008-23.296us (+one 25.18us harness-side outlier with kernel and all
// counters in band). Write injection 6.6-6.9 TB/s ≈ 99% of the HW-measured
// SM->LTS fabric write cap (~6300 B/cyc); model floor 19.4us. One block per
// (b,c) plane; 128 unique values computed once in smem (sincosf per thread);
// 16 float4 staged in registers, then burst as 16 back-to-back streaming
// STG.128 (.cs, evict-first).
//
// Complete design-space closure (all theory-predicted, all verified):
//   R2  TMA bulk stores:            -10% — LTS cap is path-independent
//   R4  8-deep bursts, occ 81%:     -19% — stores need burst depth, not
//                                   latency hiding; low occ is fine
//   R6  32-deep bursts, 1024 CTAs:  kernel-neutral, e2e -8% (wave tail)
//   R11 STG.256 (v8.f32):           neutral — issue% 12.4->10.6, BW flat;
//                                   proves the cap is fabric, not dispatch
//   R1->R3 .cs eviction hint:       +9% (kept)
//   R3/R5/R7/R8/R10/R13/R14:        at the fabric floor.
//   Rejected on model: st.global.wt (~2x worse, DRAM-bound), persistent
//   CTAs / 512-thread blocks (isomorphic stream structure, zero upside).

__global__ __launch_bounds__(256) void pe2d_kernel(float* __restrict__ out) {
    const int bc  = blockIdx.x;       // b*256 + c
    const int c   = bc & 255;
    const int tid = threadIdx.x;

    __shared__ float s[128];

    if (tid < 128) {
        const int cc    = c & 127;        // channel within half
        const int pairk = cc >> 1;        // floor(cc/2)
        const float LOG2_10000 = 13.28771237954945f;
        float inv_dim = exp2f(-(float)pairk * (LOG2_10000 / 128.0f));
        float arg = (float)tid * inv_dim; // tid = position (i or j)
        float sv, cv;
        sincosf(arg, &sv, &cv);
        s[tid] = (cc & 1) ? cv : sv;
    }
    __syncthreads();

    // Per-thread: 16 float4 stores, consecutive lanes -> consecutive float4
    // (512B per warp per store, fully coalesced). Stage all values in
    // registers FIRST, then burst the 16 streaming stores back-to-back so the
    // LSU/L2 write queue stays saturated with no interleaved LDS/index math.
    float4 v[16];
    if (c < 128) {
        // value constant along j: row index = idx4 >> 5
        #pragma unroll
        for (int t = 0; t < 16; t++) {
            const int row = (tid + t * 256) >> 5;   // warp-uniform
            const float x = s[row];                 // smem broadcast
            v[t] = make_float4(x, x, x, x);
        }
    } else {
        // value varies along j only: every row replicates s[0..127]
        const float4* s4 = reinterpret_cast<const float4*>(s);
        #pragma unroll
        for (int t = 0; t < 16; t++) {
            v[t] = s4[(tid + t * 256) & 31];        // conflict-free LDS.128
        }
    }

    float4* outp = reinterpret_cast<float4*>(out) + (size_t)bc * 4096 + tid;
    #pragma unroll
    for (int t = 0; t < 16; t++) {
        __stcs(outp + t * 256, v[t]);               // st.global.cs.v4 (evict-first)
    }
}

extern "C" void kernel_launch(void* const* d_in, const int* in_sizes, int n_in,
                              void* d_out, int out_size) {
    (void)d_in; (void)in_sizes; (void)n_in; (void)out_size;
    // 8 batches * 256 channels = 2048 planes
    pe2d_kernel<<<2048, 256>>>((float*)d_out);
}

// round 17
// speedup vs baseline: 1.0946x; 1.0014x over previous
#include <cuda_runtime.h>
#include <cuda_bf16.h>

// out shape: (B=8, C=256, H=128, W=128) fp32, row-major. Output is independent
// of the input tensor and identical across batches:
//   out[b,c,i,j] = c<128 ? trig_c(i) : trig_{c-128}(j)
//   trig_cc(p)   = (cc even ? sin : cos)(p * 10000^(-floor(cc/2)/128))
//
// FINAL — converged, nine holds: kernel 19.55-20.29us, e2e 23.008-23.296us
// (one 25.18us harness outlier, confirmed noise by identical-source re-bench).
// Write injection 6.6-6.9 TB/s ≈ 99% of the HW-measured SM->LTS fabric write
// cap (~6300 B/cyc); model floor 19.4us, best observed 19.552us. One block
// per (b,c) plane; 128 unique values computed once in smem (sincosf per
// thread); 16 float4 staged in registers, then burst as 16 back-to-back
// streaming STG.128 (.cs, evict-first).
//
// Complete design-space closure (all theory-predicted, all verified):
//   R2  TMA bulk stores:            -10% — LTS cap is path-independent
//   R4  8-deep bursts, occ 81%:     -19% — stores need burst depth, not
//                                   latency hiding; low occ is fine
//   R6  32-deep bursts, 1024 CTAs:  kernel-neutral, e2e -8% (wave tail)
//   R11 STG.256 (v8.f32):           neutral — issue% 12.4->10.6, BW flat;
//                                   proves the cap is fabric, not dispatch
//   R1->R3 .cs eviction hint:       +9% (kept)
//   R3/R5/R7/R8/R10/R13/R14/R15:    at the fabric floor.
//   Rejected on model: st.global.wt (~2x worse, DRAM-bound), persistent
//   CTAs / 512-thread blocks (isomorphic stream structure, zero upside).

__global__ __launch_bounds__(256) void pe2d_kernel(float* __restrict__ out) {
    const int bc  = blockIdx.x;       // b*256 + c
    const int c   = bc & 255;
    const int tid = threadIdx.x;

    __shared__ float s[128];

    if (tid < 128) {
        const int cc    = c & 127;        // channel within half
        const int pairk = cc >> 1;        // floor(cc/2)
        const float LOG2_10000 = 13.28771237954945f;
        float inv_dim = exp2f(-(float)pairk * (LOG2_10000 / 128.0f));
        float arg = (float)tid * inv_dim; // tid = position (i or j)
        float sv, cv;
        sincosf(arg, &sv, &cv);
        s[tid] = (cc & 1) ? cv : sv;
    }
    __syncthreads();

    // Per-thread: 16 float4 stores, consecutive lanes -> consecutive float4
    // (512B per warp per store, fully coalesced). Stage all values in
    // registers FIRST, then burst the 16 streaming stores back-to-back so the
    // LSU/L2 write queue stays saturated with no interleaved LDS/index math.
    float4 v[16];
    if (c < 128) {
        // value constant along j: row index = idx4 >> 5
        #pragma unroll
        for (int t = 0; t < 16; t++) {
            const int row = (tid + t * 256) >> 5;   // warp-uniform
            const float x = s[row];                 // smem broadcast
            v[t] = make_float4(x, x, x, x);
        }
    } else {
        // value varies along j only: every row replicates s[0..127]
        const float4* s4 = reinterpret_cast<const float4*>(s);
        #pragma unroll
        for (int t = 0; t < 16; t++) {
            v[t] = s4[(tid + t * 256) & 31];        // conflict-free LDS.128
        }
    }

    float4* outp = reinterpret_cast<float4*>(out) + (size_t)bc * 4096 + tid;
    #pragma unroll
    for (int t = 0; t < 16; t++) {
        __stcs(outp + t * 256, v[t]);               // st.global.cs.v4 (evict-first)
    }
}

extern "C" void kernel_launch(void* const* d_in, const int* in_sizes, int n_in,
                              void* d_out, int out_size) {
    (void)d_in; (void)in_sizes; (void)n_in; (void)out_size;
    // 8 batches * 256 channels = 2048 planes
    pe2d_kernel<<<2048, 256>>>((float*)d_out);
}